// round 12
// baseline (speedup 1.0000x reference)
#include <cuda_runtime.h>
#include <cuda_fp16.h>
#include <stdint.h>

// ============================================================================
// QuaternionLSTM single step, h0=c0=0 (uh_* dead; forget-gate columns dropped):
//   Z = x @ W1 + b1  (W1 = quaternion-expanded wx, gates {i,o,a}, N=768)
//   H = sigmoid(z_o) * tanh( sigmoid(z_i) * tanh(z_a) )
//   out = H @ fco_w + fco_b
// fp16 mma.sync, f32 accum (rel_err ~4.6e-4).
// R12: phase-overlap attack on gemm1 — (a) fp32->fp16 A conversion for chunk
// s+1 runs concurrently with MMAs of chunk s (double-buffered f16A, single
// barrier/chunk); (b) warps desynchronized (kk order xor wn, mi start rotated
// by wid) so LDSM and MMA phases of different warps overlap.
// ============================================================================

#define B_DIM 32768
#define F_DIM 1024
#define H_DIM 256
#define N1G   768            // 3 gates x 256

__device__ __align__(16) __half g_w1[F_DIM * N1G];           // [k][n_perm]
__device__ float g_b1[N1G];
__device__ __align__(16) __half g_h[(size_t)B_DIM * H_DIM];
__device__ __align__(16) __half g_f2[H_DIM * H_DIM];          // [k][n]

// ---------------------------------------------------------------------------
__device__ __forceinline__ uint32_t smem_u32(const void* p) {
    uint32_t a;
    asm("{ .reg .u64 t; cvta.to.shared.u64 t, %1; cvt.u32.u64 %0, t; }" : "=r"(a) : "l"(p));
    return a;
}

#define LDSM_X4(r, a) \
    asm volatile("ldmatrix.sync.aligned.m8n8.x4.shared.b16 {%0,%1,%2,%3}, [%4];" \
        : "=r"((r)[0]), "=r"((r)[1]), "=r"((r)[2]), "=r"((r)[3]) : "r"(a))
#define LDSM_X4T(r, a) \
    asm volatile("ldmatrix.sync.aligned.m8n8.x4.trans.shared.b16 {%0,%1,%2,%3}, [%4];" \
        : "=r"((r)[0]), "=r"((r)[1]), "=r"((r)[2]), "=r"((r)[3]) : "r"(a))
#define MMA_F16(d, a, b) \
    asm volatile("mma.sync.aligned.m16n8k16.row.col.f32.f16.f16.f32 " \
        "{%0,%1,%2,%3}, {%4,%5,%6,%7}, {%8,%9}, {%0,%1,%2,%3};" \
        : "+f"((d)[0]), "+f"((d)[1]), "+f"((d)[2]), "+f"((d)[3]) \
        : "r"((a)[0]), "r"((a)[1]), "r"((a)[2]), "r"((a)[3]), "r"((b)[0]), "r"((b)[1]))
#define CP_ASYNC16(dst, src) \
    asm volatile("cp.async.cg.shared.global [%0], [%1], 16;" :: "r"(dst), "l"(src) : "memory")
#define CP_COMMIT() asm volatile("cp.async.commit_group;" ::: "memory")
#define CP_WAIT(n)  asm volatile("cp.async.wait_group %0;" :: "n"(n) : "memory")

__device__ __forceinline__ float fsigm(float z) {
    return __fdividef(1.f, 1.f + __expf(-z));
}
__device__ __forceinline__ float ftanh(float x) {
    float xc = fminf(fmaxf(x, -15.f), 15.f);
    float e = __expf(2.f * xc);
    return __fdividef(e - 1.f, e + 1.f);
}

// ---------------------------------------------------------------------------
// Prep kernels
// ---------------------------------------------------------------------------
__global__ void build_w1(const float* __restrict__ wr, const float* __restrict__ wi,
                         const float* __restrict__ wj, const float* __restrict__ wk,
                         const float* __restrict__ bx) {
    int rem = blockIdx.x * blockDim.x + threadIdx.x;   // 0..767
    int f = blockIdx.y;
    int blk = rem / 24;
    int r24 = rem - blk * 24;
    int g1 = r24 >> 3, hh = r24 & 7;
    int h = blk * 8 + hh;
    int gate = g1 + 1;                      // skip forget gate (index 0)
    int qout = h >> 6, h4 = h & 63;
    int qin = f >> 8, f4 = f & 255;
    int comp = qin ^ qout;
    const float* a = (comp & 2) ? ((comp & 1) ? wk : wj)
                                : ((comp & 1) ? wi : wr);
    float w = a[gate * (256 * 64) + f4 * 64 + h4];
    float v = ((0x5390u >> ((qin << 2) + qout)) & 1u) ? -w : w;
    g_w1[f * N1G + rem] = __float2half(v);
    if (f == 0) g_b1[rem] = bx[gate * H_DIM + h];
}

__global__ void split_fco(const float* __restrict__ w) {
    int idx = blockIdx.x * blockDim.x + threadIdx.x;  // over 65536, [k][n]
    g_f2[idx] = __float2half(w[idx]);
}

// ---------------------------------------------------------------------------
// GEMM1 + overlapped fp32->fp16 A conversion + LSTM epilogue.
// CTA 128x192, K-chunk 32, 8 warps 2x4 (warp tile 64x48), 2 CTAs/SM.
// SMEM: f16A[2][10240] double buffer, 3 stages x { f32A 18432, B 12800 }.
// One barrier per chunk; conversion of chunk s+1 overlaps MMAs of chunk s.
// ---------------------------------------------------------------------------
#define F16A_SZ   10240
#define F32A_SZ   18432
#define G1_BSZ    12800
#define G1_STAGE  (F32A_SZ + G1_BSZ)              // 31232
#define G1_SOFF   (2 * F16A_SZ)                   // 20480
#define G1_SMEM   (G1_SOFF + 3 * G1_STAGE)        // 114176

__global__ __launch_bounds__(256, 2)
void gemm1_lstm(const float* __restrict__ x) {
    constexpr int NSTEPS = F_DIM / 32;            // 32
    extern __shared__ __align__(128) char smem[];
    const uint32_t sb = smem_u32(smem);
    const int tid = threadIdx.x, lane = tid & 31, wid = tid >> 5;
    const int wm = wid >> 2, wn = wid & 3;
    const int rowBase = blockIdx.y * 128, colBase = blockIdx.x * 192;

    // stage loader: f32A 1024 granules (4/thread) + B 768 granules (3/thread)
    auto load_stage = [&](int buf, int k0) {
        uint32_t base = sb + G1_SOFF + buf * G1_STAGE;
#pragma unroll
        for (int i = 0; i < 4; i++) {             // f32A: row = g>>3, c16 = g&7
            int g = i * 256 + tid;
            int row = g >> 3, c16 = g & 7;
            CP_ASYNC16(base + row * 144 + c16 * 16,
                       x + (size_t)(rowBase + row) * F_DIM + k0 + c16 * 4);
        }
#pragma unroll
        for (int i = 0; i < 3; i++) {             // B: [32 rows][24 x 16B]
            int gb = i * 256 + tid;
            int row = gb / 24, c16 = gb - row * 24;
            CP_ASYNC16(base + F32A_SZ + row * 400 + c16 * 16,
                       g_w1 + (size_t)(k0 + row) * N1G + colBase + c16 * 8);
        }
        CP_COMMIT();
    };

    // conversion: thread -> row = tid>>1, half-row (16 floats) = tid&1
    const uint32_t cvtSrcOff = G1_SOFF + (tid >> 1) * 144 + (tid & 1) * 64;
    const uint32_t cvtDstOff = (tid >> 1) * 80 + (tid & 1) * 32;
    auto convert = [&](int f32buf, int f16buf) {
        const float4* sp = (const float4*)(smem + cvtSrcOff + f32buf * G1_STAGE);
        float4 v0 = sp[0], v1 = sp[1], v2 = sp[2], v3 = sp[3];
        __half2 h[8];
        h[0] = __floats2half2_rn(v0.x, v0.y);
        h[1] = __floats2half2_rn(v0.z, v0.w);
        h[2] = __floats2half2_rn(v1.x, v1.y);
        h[3] = __floats2half2_rn(v1.z, v1.w);
        h[4] = __floats2half2_rn(v2.x, v2.y);
        h[5] = __floats2half2_rn(v2.z, v2.w);
        h[6] = __floats2half2_rn(v3.x, v3.y);
        h[7] = __floats2half2_rn(v3.z, v3.w);
        uint4* dp = (uint4*)(smem + f16buf * F16A_SZ + cvtDstOff);
        dp[0] = ((uint4*)h)[0];
        dp[1] = ((uint4*)h)[1];
    };

    float acc[4][6][4];
#pragma unroll
    for (int a = 0; a < 4; a++)
#pragma unroll
        for (int b = 0; b < 6; b++)
#pragma unroll
            for (int c = 0; c < 4; c++) acc[a][b][c] = 0.f;

    load_stage(0, 0);
    load_stage(1, 32);
    CP_WAIT(1);                     // stage 0 landed
    __syncthreads();
    convert(0, 0);                  // f16A[0] <- chunk 0

    const int miRot = wid & 3;      // desync: mi start rotated per warp
    const int kkX   = wn & 1;       // desync: kk order xored per warp

#pragma unroll 1
    for (int s = 0; s < NSTEPS; s++) {
        CP_WAIT(0);                 // stage s+1 landed (no-op on last iter)
        __syncthreads();            // conversion of s visible; prev reads done
        if (s + 2 < NSTEPS) load_stage((s + 2) % 3, (s + 2) * 32);
        if (s + 1 < NSTEPS) convert((s + 1) % 3, (s + 1) & 1);

        uint32_t f16b = sb + (s & 1) * F16A_SZ;
        uint32_t bstage = sb + G1_SOFF + (s % 3) * G1_STAGE + F32A_SZ;
#pragma unroll
        for (int kk2 = 0; kk2 < 2; kk2++) {
            int kk = kk2 ^ kkX;
            uint32_t bf[3][4];
            uint32_t brow = bstage + (kk * 16 + (lane & 15)) * 400;
#pragma unroll
            for (int p = 0; p < 3; p++)
                LDSM_X4T(bf[p], brow + (wn * 48 + p * 16 + (lane >> 4) * 8) * 2);
#pragma unroll
            for (int mi2 = 0; mi2 < 4; mi2++) {
                int mi = (mi2 + miRot) & 3;
                uint32_t af[4];
                LDSM_X4(af, f16b + (wm * 64 + mi * 16 + (lane & 15)) * 80
                            + (kk * 16 + (lane >> 4) * 8) * 2);
#pragma unroll
                for (int ni = 0; ni < 6; ni++)
                    MMA_F16(acc[mi][ni], af, &bf[ni >> 1][(ni & 1) * 2]);
            }
        }
    }

    // --------------------- LSTM epilogue (register-local) -------------------
    const int c0 = 2 * (lane & 3);
    const int blk0 = (colBase / 24) + wn * 2;
#pragma unroll
    for (int b = 0; b < 2; b++) {
        const int cb = colBase + wn * 48 + b * 24;
        const int h0 = (blk0 + b) * 8 + c0;
        float bi0 = g_b1[cb + c0],      bi1 = g_b1[cb + c0 + 1];
        float bo0 = g_b1[cb + 8 + c0],  bo1 = g_b1[cb + 8 + c0 + 1];
        float ba0 = g_b1[cb + 16 + c0], ba1 = g_b1[cb + 16 + c0 + 1];
#pragma unroll
        for (int mi = 0; mi < 4; mi++) {
            int r0 = rowBase + wm * 64 + mi * 16 + (lane >> 2);
#pragma unroll
            for (int rr = 0; rr < 2; rr++) {
                float zi0 = acc[mi][3 * b + 0][rr * 2 + 0] + bi0;
                float zi1 = acc[mi][3 * b + 0][rr * 2 + 1] + bi1;
                float zo0 = acc[mi][3 * b + 1][rr * 2 + 0] + bo0;
                float zo1 = acc[mi][3 * b + 1][rr * 2 + 1] + bo1;
                float za0 = acc[mi][3 * b + 2][rr * 2 + 0] + ba0;
                float za1 = acc[mi][3 * b + 2][rr * 2 + 1] + ba1;
                float hv0 = fsigm(zo0) * ftanh(fsigm(zi0) * ftanh(za0));
                float hv1 = fsigm(zo1) * ftanh(fsigm(zi1) * ftanh(za1));
                size_t m = (size_t)(r0 + rr * 8);
                *(__half2*)&g_h[m * H_DIM + h0] =
                    __halves2half2(__float2half(hv0), __float2half(hv1));
            }
        }
    }
}

// ---------------------------------------------------------------------------
// GEMM2: out = H @ fco_w + fco_b. CTA 128x128, K=256, warp tile 64x32,
// 4 stages / prefetch-3, warp desync on kk/mi.
// ---------------------------------------------------------------------------
#define G2_BOFF   10240
#define G2_STAGE  18944
#define G2_SMEM   (4 * G2_STAGE)

__global__ __launch_bounds__(256, 2)
void gemm2(const float* __restrict__ biasg, float* __restrict__ outp) {
    constexpr int NB = H_DIM, NSTEPS = H_DIM / 32;
    extern __shared__ __align__(128) char smem[];
    const uint32_t sb = smem_u32(smem);
    const int tid = threadIdx.x, lane = tid & 31, wid = tid >> 5;
    const int wm = wid >> 2, wn = wid & 3;
    const int rowBase = blockIdx.y * 128, colBase = blockIdx.x * 128;

    auto load_stage = [&](int buf, int k0) {
        uint32_t base = sb + buf * G2_STAGE;
#pragma unroll
        for (int i = 0; i < 4; i++) {
            int g = i * 256 + tid;
            const __half* src;
            uint32_t dst;
            if (g < 512) {
                int row = g >> 2, c16 = g & 3;
                src = g_h + (size_t)(rowBase + row) * H_DIM + k0 + c16 * 8;
                dst = base + row * 80 + c16 * 16;
            } else {
                int gb = g - 512;
                int row = gb >> 4, c16 = gb & 15;
                src = g_f2 + (size_t)(k0 + row) * NB + colBase + c16 * 8;
                dst = base + G2_BOFF + row * 272 + c16 * 16;
            }
            CP_ASYNC16(dst, src);
        }
        CP_COMMIT();
    };

    float acc[4][4][4];
#pragma unroll
    for (int a = 0; a < 4; a++)
#pragma unroll
        for (int b = 0; b < 4; b++)
#pragma unroll
            for (int c = 0; c < 4; c++) acc[a][b][c] = 0.f;

    load_stage(0, 0);
    load_stage(1, 32);
    load_stage(2, 64);

    const int miRot = wid & 3;
    const int kkX   = wn & 1;

#pragma unroll 1
    for (int s = 0; s < NSTEPS; s++) {
        if (s + 2 < NSTEPS)      CP_WAIT(2);
        else if (s + 1 < NSTEPS) CP_WAIT(1);
        else                     CP_WAIT(0);
        __syncthreads();
        if (s + 3 < NSTEPS) load_stage((s + 3) & 3, (s + 3) * 32);

        uint32_t base = sb + (s & 3) * G2_STAGE;
#pragma unroll
        for (int kk2 = 0; kk2 < 2; kk2++) {
            int kk = kk2 ^ kkX;
            uint32_t bf[2][4];
#pragma unroll
            for (int p = 0; p < 2; p++)
                LDSM_X4T(bf[p], base + G2_BOFF + (kk * 16 + (lane & 15)) * 272
                               + (wn * 32 + p * 16 + (lane >> 4) * 8) * 2);
#pragma unroll
            for (int mi2 = 0; mi2 < 4; mi2++) {
                int mi = (mi2 + miRot) & 3;
                uint32_t af[4];
                LDSM_X4(af, base + (wm * 64 + mi * 16 + (lane & 15)) * 80
                            + (kk * 16 + (lane >> 4) * 8) * 2);
#pragma unroll
                for (int ni = 0; ni < 4; ni++)
                    MMA_F16(acc[mi][ni], af, &bf[ni >> 1][(ni & 1) * 2]);
            }
        }
    }

#pragma unroll
    for (int mi = 0; mi < 4; mi++) {
        int r0 = rowBase + wm * 64 + mi * 16 + (lane >> 2);
#pragma unroll
        for (int ni = 0; ni < 4; ni++) {
            int col = colBase + wn * 32 + ni * 8 + (lane & 3) * 2;
            float b0 = biasg[col], b1 = biasg[col + 1];
            float2 o0 = {acc[mi][ni][0] + b0, acc[mi][ni][1] + b1};
            float2 o1 = {acc[mi][ni][2] + b0, acc[mi][ni][3] + b1};
            *(float2*)&outp[(size_t)r0 * NB + col] = o0;
            *(float2*)&outp[(size_t)(r0 + 8) * NB + col] = o1;
        }
    }
}

// ---------------------------------------------------------------------------
extern "C" void kernel_launch(void* const* d_in, const int* in_sizes, int n_in,
                              void* d_out, int out_size) {
    const float* x     = (const float*)d_in[0];
    const float* wx_r  = (const float*)d_in[1];
    const float* wx_i  = (const float*)d_in[2];
    const float* wx_j  = (const float*)d_in[3];
    const float* wx_k  = (const float*)d_in[4];
    const float* bx    = (const float*)d_in[5];
    const float* fco_w = (const float*)d_in[10];
    const float* fco_b = (const float*)d_in[11];
    float* out = (float*)d_out;

    build_w1<<<dim3(3, F_DIM), 256>>>(wx_r, wx_i, wx_j, wx_k, bx);
    split_fco<<<(H_DIM * H_DIM) / 256, 256>>>(fco_w);

    cudaFuncSetAttribute(gemm1_lstm,
                         cudaFuncAttributeMaxDynamicSharedMemorySize, G1_SMEM);
    cudaFuncSetAttribute(gemm2,
                         cudaFuncAttributeMaxDynamicSharedMemorySize, G2_SMEM);

    gemm1_lstm<<<dim3(N1G / 192, B_DIM / 128), 256, G1_SMEM>>>(x);
    gemm2<<<dim3(H_DIM / 128, B_DIM / 128), 256, G2_SMEM>>>(fco_b, out);
}

// round 13
// speedup vs baseline: 4.7986x; 4.7986x over previous
#include <cuda_runtime.h>
#include <cuda_fp16.h>
#include <stdint.h>

// ============================================================================
// QuaternionLSTM single step, h0=c0=0 (uh_* dead; forget-gate columns dropped):
//   Z = x @ W1 + b1  (W1 = quaternion-expanded wx, gates {i,o,a}, N=768)
//   H = sigmoid(z_o) * tanh( sigmoid(z_i) * tanh(z_a) )
//   out = H @ fco_w + fco_b
// fp16 mma.sync, f32 accum (rel_err ~4.6e-4).
// R13: surgical revert of R12's "warp desync" (runtime-indexed register array
// -> ptxas spilled accumulators to local mem, 5x regression). Keeps the sound
// part: overlapped fp32->fp16 A conversion (double-buffered f16A, one barrier
// per chunk). gemm2 = R11 4-stage verbatim. ALL loop indices static.
// ============================================================================

#define B_DIM 32768
#define F_DIM 1024
#define H_DIM 256
#define N1G   768            // 3 gates x 256

__device__ __align__(16) __half g_w1[F_DIM * N1G];           // [k][n_perm]
__device__ float g_b1[N1G];
__device__ __align__(16) __half g_h[(size_t)B_DIM * H_DIM];
__device__ __align__(16) __half g_f2[H_DIM * H_DIM];          // [k][n]

// ---------------------------------------------------------------------------
__device__ __forceinline__ uint32_t smem_u32(const void* p) {
    uint32_t a;
    asm("{ .reg .u64 t; cvta.to.shared.u64 t, %1; cvt.u32.u64 %0, t; }" : "=r"(a) : "l"(p));
    return a;
}

#define LDSM_X4(r, a) \
    asm volatile("ldmatrix.sync.aligned.m8n8.x4.shared.b16 {%0,%1,%2,%3}, [%4];" \
        : "=r"((r)[0]), "=r"((r)[1]), "=r"((r)[2]), "=r"((r)[3]) : "r"(a))
#define LDSM_X4T(r, a) \
    asm volatile("ldmatrix.sync.aligned.m8n8.x4.trans.shared.b16 {%0,%1,%2,%3}, [%4];" \
        : "=r"((r)[0]), "=r"((r)[1]), "=r"((r)[2]), "=r"((r)[3]) : "r"(a))
#define MMA_F16(d, a, b) \
    asm volatile("mma.sync.aligned.m16n8k16.row.col.f32.f16.f16.f32 " \
        "{%0,%1,%2,%3}, {%4,%5,%6,%7}, {%8,%9}, {%0,%1,%2,%3};" \
        : "+f"((d)[0]), "+f"((d)[1]), "+f"((d)[2]), "+f"((d)[3]) \
        : "r"((a)[0]), "r"((a)[1]), "r"((a)[2]), "r"((a)[3]), "r"((b)[0]), "r"((b)[1]))
#define CP_ASYNC16(dst, src) \
    asm volatile("cp.async.cg.shared.global [%0], [%1], 16;" :: "r"(dst), "l"(src) : "memory")
#define CP_COMMIT() asm volatile("cp.async.commit_group;" ::: "memory")
#define CP_WAIT(n)  asm volatile("cp.async.wait_group %0;" :: "n"(n) : "memory")

__device__ __forceinline__ float fsigm(float z) {
    return __fdividef(1.f, 1.f + __expf(-z));
}
__device__ __forceinline__ float ftanh(float x) {
    float xc = fminf(fmaxf(x, -15.f), 15.f);
    float e = __expf(2.f * xc);
    return __fdividef(e - 1.f, e + 1.f);
}

// ---------------------------------------------------------------------------
// Prep kernels
// ---------------------------------------------------------------------------
__global__ void build_w1(const float* __restrict__ wr, const float* __restrict__ wi,
                         const float* __restrict__ wj, const float* __restrict__ wk,
                         const float* __restrict__ bx) {
    int rem = blockIdx.x * blockDim.x + threadIdx.x;   // 0..767
    int f = blockIdx.y;
    int blk = rem / 24;
    int r24 = rem - blk * 24;
    int g1 = r24 >> 3, hh = r24 & 7;
    int h = blk * 8 + hh;
    int gate = g1 + 1;                      // skip forget gate (index 0)
    int qout = h >> 6, h4 = h & 63;
    int qin = f >> 8, f4 = f & 255;
    int comp = qin ^ qout;
    const float* a = (comp & 2) ? ((comp & 1) ? wk : wj)
                                : ((comp & 1) ? wi : wr);
    float w = a[gate * (256 * 64) + f4 * 64 + h4];
    float v = ((0x5390u >> ((qin << 2) + qout)) & 1u) ? -w : w;
    g_w1[f * N1G + rem] = __float2half(v);
    if (f == 0) g_b1[rem] = bx[gate * H_DIM + h];
}

__global__ void split_fco(const float* __restrict__ w) {
    int idx = blockIdx.x * blockDim.x + threadIdx.x;  // over 65536, [k][n]
    g_f2[idx] = __float2half(w[idx]);
}

// ---------------------------------------------------------------------------
// GEMM1 + overlapped fp32->fp16 A conversion + LSTM epilogue.
// CTA 128x192, K-chunk 32, 8 warps 2x4 (warp tile 64x48), 2 CTAs/SM.
// SMEM: f16A[2][10240] double buffer, 3 stages x { f32A 18432, B 12800 }.
// One barrier per chunk; conversion of chunk s+1 overlaps MMAs of chunk s.
// ---------------------------------------------------------------------------
#define F16A_SZ   10240
#define F32A_SZ   18432
#define G1_BSZ    12800
#define G1_STAGE  (F32A_SZ + G1_BSZ)              // 31232
#define G1_SOFF   (2 * F16A_SZ)                   // 20480
#define G1_SMEM   (G1_SOFF + 3 * G1_STAGE)        // 114176

__global__ __launch_bounds__(256, 2)
void gemm1_lstm(const float* __restrict__ x) {
    constexpr int NSTEPS = F_DIM / 32;            // 32
    extern __shared__ __align__(128) char smem[];
    const uint32_t sb = smem_u32(smem);
    const int tid = threadIdx.x, lane = tid & 31, wid = tid >> 5;
    const int wm = wid >> 2, wn = wid & 3;
    const int rowBase = blockIdx.y * 128, colBase = blockIdx.x * 192;

    // stage loader: f32A 1024 granules (4/thread) + B 768 granules (3/thread)
    auto load_stage = [&](int buf, int k0) {
        uint32_t base = sb + G1_SOFF + buf * G1_STAGE;
#pragma unroll
        for (int i = 0; i < 4; i++) {             // f32A: row = g>>3, c16 = g&7
            int g = i * 256 + tid;
            int row = g >> 3, c16 = g & 7;
            CP_ASYNC16(base + row * 144 + c16 * 16,
                       x + (size_t)(rowBase + row) * F_DIM + k0 + c16 * 4);
        }
#pragma unroll
        for (int i = 0; i < 3; i++) {             // B: [32 rows][24 x 16B]
            int gb = i * 256 + tid;
            int row = gb / 24, c16 = gb - row * 24;
            CP_ASYNC16(base + F32A_SZ + row * 400 + c16 * 16,
                       g_w1 + (size_t)(k0 + row) * N1G + colBase + c16 * 8);
        }
        CP_COMMIT();
    };

    // conversion: thread -> row = tid>>1, half-row (16 floats) = tid&1
    const uint32_t cvtSrcOff = G1_SOFF + (tid >> 1) * 144 + (tid & 1) * 64;
    const uint32_t cvtDstOff = (tid >> 1) * 80 + (tid & 1) * 32;
    auto convert = [&](int f32buf, int f16buf) {
        const float4* sp = (const float4*)(smem + cvtSrcOff + f32buf * G1_STAGE);
        float4 v0 = sp[0], v1 = sp[1], v2 = sp[2], v3 = sp[3];
        __half2 h[8];
        h[0] = __floats2half2_rn(v0.x, v0.y);
        h[1] = __floats2half2_rn(v0.z, v0.w);
        h[2] = __floats2half2_rn(v1.x, v1.y);
        h[3] = __floats2half2_rn(v1.z, v1.w);
        h[4] = __floats2half2_rn(v2.x, v2.y);
        h[5] = __floats2half2_rn(v2.z, v2.w);
        h[6] = __floats2half2_rn(v3.x, v3.y);
        h[7] = __floats2half2_rn(v3.z, v3.w);
        uint4* dp = (uint4*)(smem + f16buf * F16A_SZ + cvtDstOff);
        dp[0] = ((uint4*)h)[0];
        dp[1] = ((uint4*)h)[1];
    };

    float acc[4][6][4];
#pragma unroll
    for (int a = 0; a < 4; a++)
#pragma unroll
        for (int b = 0; b < 6; b++)
#pragma unroll
            for (int c = 0; c < 4; c++) acc[a][b][c] = 0.f;

    load_stage(0, 0);
    load_stage(1, 32);
    CP_WAIT(1);                     // stage 0 landed
    __syncthreads();
    convert(0, 0);                  // f16A[0] <- chunk 0

#pragma unroll 1
    for (int s = 0; s < NSTEPS; s++) {
        CP_WAIT(0);                 // stage s+1 landed (no-op on last iter)
        __syncthreads();            // conversion of s visible; prev reads done
        if (s + 2 < NSTEPS) load_stage((s + 2) % 3, (s + 2) * 32);
        if (s + 1 < NSTEPS) convert((s + 1) % 3, (s + 1) & 1);

        uint32_t f16b = sb + (s & 1) * F16A_SZ;
        uint32_t bstage = sb + G1_SOFF + (s % 3) * G1_STAGE + F32A_SZ;
#pragma unroll
        for (int kk = 0; kk < 2; kk++) {
            uint32_t bf[3][4];
            uint32_t brow = bstage + (kk * 16 + (lane & 15)) * 400;
#pragma unroll
            for (int p = 0; p < 3; p++)
                LDSM_X4T(bf[p], brow + (wn * 48 + p * 16 + (lane >> 4) * 8) * 2);
#pragma unroll
            for (int mi = 0; mi < 4; mi++) {
                uint32_t af[4];
                LDSM_X4(af, f16b + (wm * 64 + mi * 16 + (lane & 15)) * 80
                            + (kk * 16 + (lane >> 4) * 8) * 2);
#pragma unroll
                for (int ni = 0; ni < 6; ni++)
                    MMA_F16(acc[mi][ni], af, &bf[ni >> 1][(ni & 1) * 2]);
            }
        }
    }

    // --------------------- LSTM epilogue (register-local) -------------------
    const int c0 = 2 * (lane & 3);
    const int blk0 = (colBase / 24) + wn * 2;
#pragma unroll
    for (int b = 0; b < 2; b++) {
        const int cb = colBase + wn * 48 + b * 24;
        const int h0 = (blk0 + b) * 8 + c0;
        float bi0 = g_b1[cb + c0],      bi1 = g_b1[cb + c0 + 1];
        float bo0 = g_b1[cb + 8 + c0],  bo1 = g_b1[cb + 8 + c0 + 1];
        float ba0 = g_b1[cb + 16 + c0], ba1 = g_b1[cb + 16 + c0 + 1];
#pragma unroll
        for (int mi = 0; mi < 4; mi++) {
            int r0 = rowBase + wm * 64 + mi * 16 + (lane >> 2);
#pragma unroll
            for (int rr = 0; rr < 2; rr++) {
                float zi0 = acc[mi][3 * b + 0][rr * 2 + 0] + bi0;
                float zi1 = acc[mi][3 * b + 0][rr * 2 + 1] + bi1;
                float zo0 = acc[mi][3 * b + 1][rr * 2 + 0] + bo0;
                float zo1 = acc[mi][3 * b + 1][rr * 2 + 1] + bo1;
                float za0 = acc[mi][3 * b + 2][rr * 2 + 0] + ba0;
                float za1 = acc[mi][3 * b + 2][rr * 2 + 1] + ba1;
                float hv0 = fsigm(zo0) * ftanh(fsigm(zi0) * ftanh(za0));
                float hv1 = fsigm(zo1) * ftanh(fsigm(zi1) * ftanh(za1));
                size_t m = (size_t)(r0 + rr * 8);
                *(__half2*)&g_h[m * H_DIM + h0] =
                    __halves2half2(__float2half(hv0), __float2half(hv1));
            }
        }
    }
}

// ---------------------------------------------------------------------------
// GEMM2 (R11 verbatim): out = H @ fco_w + fco_b. CTA 128x128, K=256,
// warp tile 64x32, 4 stages / prefetch-3. No desync.
// ---------------------------------------------------------------------------
#define G2_BOFF   10240
#define G2_STAGE  18944
#define G2_SMEM   (4 * G2_STAGE)

__global__ __launch_bounds__(256, 2)
void gemm2(const float* __restrict__ biasg, float* __restrict__ outp) {
    constexpr int NB = H_DIM, NSTEPS = H_DIM / 32;
    extern __shared__ __align__(128) char smem[];
    const uint32_t sb = smem_u32(smem);
    const int tid = threadIdx.x, lane = tid & 31, wid = tid >> 5;
    const int wm = wid >> 2, wn = wid & 3;
    const int rowBase = blockIdx.y * 128, colBase = blockIdx.x * 128;

    auto load_stage = [&](int buf, int k0) {
        uint32_t base = sb + buf * G2_STAGE;
#pragma unroll
        for (int i = 0; i < 4; i++) {
            int g = i * 256 + tid;
            const __half* src;
            uint32_t dst;
            if (g < 512) {
                int row = g >> 2, c16 = g & 3;
                src = g_h + (size_t)(rowBase + row) * H_DIM + k0 + c16 * 8;
                dst = base + row * 80 + c16 * 16;
            } else {
                int gb = g - 512;
                int row = gb >> 4, c16 = gb & 15;
                src = g_f2 + (size_t)(k0 + row) * NB + colBase + c16 * 8;
                dst = base + G2_BOFF + row * 272 + c16 * 16;
            }
            CP_ASYNC16(dst, src);
        }
        CP_COMMIT();
    };

    float acc[4][4][4];
#pragma unroll
    for (int a = 0; a < 4; a++)
#pragma unroll
        for (int b = 0; b < 4; b++)
#pragma unroll
            for (int c = 0; c < 4; c++) acc[a][b][c] = 0.f;

    load_stage(0, 0);
    load_stage(1, 32);
    load_stage(2, 64);

#pragma unroll 1
    for (int s = 0; s < NSTEPS; s++) {
        if (s + 2 < NSTEPS)      CP_WAIT(2);
        else if (s + 1 < NSTEPS) CP_WAIT(1);
        else                     CP_WAIT(0);
        __syncthreads();
        if (s + 3 < NSTEPS) load_stage((s + 3) & 3, (s + 3) * 32);

        uint32_t base = sb + (s & 3) * G2_STAGE;
#pragma unroll
        for (int kk = 0; kk < 2; kk++) {
            uint32_t bf[2][4];
#pragma unroll
            for (int p = 0; p < 2; p++)
                LDSM_X4T(bf[p], base + G2_BOFF + (kk * 16 + (lane & 15)) * 272
                               + (wn * 32 + p * 16 + (lane >> 4) * 8) * 2);
#pragma unroll
            for (int mi = 0; mi < 4; mi++) {
                uint32_t af[4];
                LDSM_X4(af, base + (wm * 64 + mi * 16 + (lane & 15)) * 80
                            + (kk * 16 + (lane >> 4) * 8) * 2);
#pragma unroll
                for (int ni = 0; ni < 4; ni++)
                    MMA_F16(acc[mi][ni], af, &bf[ni >> 1][(ni & 1) * 2]);
            }
        }
    }

#pragma unroll
    for (int mi = 0; mi < 4; mi++) {
        int r0 = rowBase + wm * 64 + mi * 16 + (lane >> 2);
#pragma unroll
        for (int ni = 0; ni < 4; ni++) {
            int col = colBase + wn * 32 + ni * 8 + (lane & 3) * 2;
            float b0 = biasg[col], b1 = biasg[col + 1];
            float2 o0 = {acc[mi][ni][0] + b0, acc[mi][ni][1] + b1};
            float2 o1 = {acc[mi][ni][2] + b0, acc[mi][ni][3] + b1};
            *(float2*)&outp[(size_t)r0 * NB + col] = o0;
            *(float2*)&outp[(size_t)(r0 + 8) * NB + col] = o1;
        }
    }
}

// ---------------------------------------------------------------------------
extern "C" void kernel_launch(void* const* d_in, const int* in_sizes, int n_in,
                              void* d_out, int out_size) {
    const float* x     = (const float*)d_in[0];
    const float* wx_r  = (const float*)d_in[1];
    const float* wx_i  = (const float*)d_in[2];
    const float* wx_j  = (const float*)d_in[3];
    const float* wx_k  = (const float*)d_in[4];
    const float* bx    = (const float*)d_in[5];
    const float* fco_w = (const float*)d_in[10];
    const float* fco_b = (const float*)d_in[11];
    float* out = (float*)d_out;

    build_w1<<<dim3(3, F_DIM), 256>>>(wx_r, wx_i, wx_j, wx_k, bx);
    split_fco<<<(H_DIM * H_DIM) / 256, 256>>>(fco_w);

    cudaFuncSetAttribute(gemm1_lstm,
                         cudaFuncAttributeMaxDynamicSharedMemorySize, G1_SMEM);
    cudaFuncSetAttribute(gemm2,
                         cudaFuncAttributeMaxDynamicSharedMemorySize, G2_SMEM);

    gemm1_lstm<<<dim3(N1G / 192, B_DIM / 128), 256, G1_SMEM>>>(x);
    gemm2<<<dim3(H_DIM / 128, B_DIM / 128), 256, G2_SMEM>>>(fco_b, out);
}

// round 14
// speedup vs baseline: 4.8398x; 1.0086x over previous
#include <cuda_runtime.h>
#include <cuda_fp16.h>
#include <stdint.h>

// ============================================================================
// QuaternionLSTM single step, h0=c0=0 (uh_* dead; forget-gate columns dropped):
//   Z = x @ W1 + b1  (W1 = quaternion-expanded wx, gates {i,o,a}, N=768)
//   H = sigmoid(z_o) * tanh( sigmoid(z_i) * tanh(z_a) )
//   out = H @ fco_w + fco_b
// fp16 mma.sync, f32 accum (rel_err ~4.6e-4).
// R14: fixes R13's pipeline drain — issue load(s+2) BEFORE cp.async.wait_group(1)
// so stage s+1 is guaranteed landed (for the overlapped convert) while stage
// s+2 stays in flight. One barrier per chunk, conversion overlaps MMAs,
// prefetch depth restored. gemm2 = R11 4-stage verbatim.
// ============================================================================

#define B_DIM 32768
#define F_DIM 1024
#define H_DIM 256
#define N1G   768            // 3 gates x 256

__device__ __align__(16) __half g_w1[F_DIM * N1G];           // [k][n_perm]
__device__ float g_b1[N1G];
__device__ __align__(16) __half g_h[(size_t)B_DIM * H_DIM];
__device__ __align__(16) __half g_f2[H_DIM * H_DIM];          // [k][n]

// ---------------------------------------------------------------------------
__device__ __forceinline__ uint32_t smem_u32(const void* p) {
    uint32_t a;
    asm("{ .reg .u64 t; cvta.to.shared.u64 t, %1; cvt.u32.u64 %0, t; }" : "=r"(a) : "l"(p));
    return a;
}

#define LDSM_X4(r, a) \
    asm volatile("ldmatrix.sync.aligned.m8n8.x4.shared.b16 {%0,%1,%2,%3}, [%4];" \
        : "=r"((r)[0]), "=r"((r)[1]), "=r"((r)[2]), "=r"((r)[3]) : "r"(a))
#define LDSM_X4T(r, a) \
    asm volatile("ldmatrix.sync.aligned.m8n8.x4.trans.shared.b16 {%0,%1,%2,%3}, [%4];" \
        : "=r"((r)[0]), "=r"((r)[1]), "=r"((r)[2]), "=r"((r)[3]) : "r"(a))
#define MMA_F16(d, a, b) \
    asm volatile("mma.sync.aligned.m16n8k16.row.col.f32.f16.f16.f32 " \
        "{%0,%1,%2,%3}, {%4,%5,%6,%7}, {%8,%9}, {%0,%1,%2,%3};" \
        : "+f"((d)[0]), "+f"((d)[1]), "+f"((d)[2]), "+f"((d)[3]) \
        : "r"((a)[0]), "r"((a)[1]), "r"((a)[2]), "r"((a)[3]), "r"((b)[0]), "r"((b)[1]))
#define CP_ASYNC16(dst, src) \
    asm volatile("cp.async.cg.shared.global [%0], [%1], 16;" :: "r"(dst), "l"(src) : "memory")
#define CP_COMMIT() asm volatile("cp.async.commit_group;" ::: "memory")
#define CP_WAIT(n)  asm volatile("cp.async.wait_group %0;" :: "n"(n) : "memory")

__device__ __forceinline__ float fsigm(float z) {
    return __fdividef(1.f, 1.f + __expf(-z));
}
__device__ __forceinline__ float ftanh(float x) {
    float xc = fminf(fmaxf(x, -15.f), 15.f);
    float e = __expf(2.f * xc);
    return __fdividef(e - 1.f, e + 1.f);
}

// ---------------------------------------------------------------------------
// Prep kernels
// ---------------------------------------------------------------------------
__global__ void build_w1(const float* __restrict__ wr, const float* __restrict__ wi,
                         const float* __restrict__ wj, const float* __restrict__ wk,
                         const float* __restrict__ bx) {
    int rem = blockIdx.x * blockDim.x + threadIdx.x;   // 0..767
    int f = blockIdx.y;
    int blk = rem / 24;
    int r24 = rem - blk * 24;
    int g1 = r24 >> 3, hh = r24 & 7;
    int h = blk * 8 + hh;
    int gate = g1 + 1;                      // skip forget gate (index 0)
    int qout = h >> 6, h4 = h & 63;
    int qin = f >> 8, f4 = f & 255;
    int comp = qin ^ qout;
    const float* a = (comp & 2) ? ((comp & 1) ? wk : wj)
                                : ((comp & 1) ? wi : wr);
    float w = a[gate * (256 * 64) + f4 * 64 + h4];
    float v = ((0x5390u >> ((qin << 2) + qout)) & 1u) ? -w : w;
    g_w1[f * N1G + rem] = __float2half(v);
    if (f == 0) g_b1[rem] = bx[gate * H_DIM + h];
}

__global__ void split_fco(const float* __restrict__ w) {
    int idx = blockIdx.x * blockDim.x + threadIdx.x;  // over 65536, [k][n]
    g_f2[idx] = __float2half(w[idx]);
}

// ---------------------------------------------------------------------------
// GEMM1 + overlapped fp32->fp16 A conversion + LSTM epilogue.
// CTA 128x192, K-chunk 32, 8 warps 2x4 (warp tile 64x48), 2 CTAs/SM.
// SMEM: f16A[2][10240] double buffer, 3 stages x { f32A 18432, B 12800 }.
// Loop: sync -> issue load(s+2) -> wait(1) [stage s+1 landed, s+2 in flight]
//       -> convert(s+1) overlapped with MMAs of chunk s.
// ---------------------------------------------------------------------------
#define F16A_SZ   10240
#define F32A_SZ   18432
#define G1_BSZ    12800
#define G1_STAGE  (F32A_SZ + G1_BSZ)              // 31232
#define G1_SOFF   (2 * F16A_SZ)                   // 20480
#define G1_SMEM   (G1_SOFF + 3 * G1_STAGE)        // 114176

__global__ __launch_bounds__(256, 2)
void gemm1_lstm(const float* __restrict__ x) {
    constexpr int NSTEPS = F_DIM / 32;            // 32
    extern __shared__ __align__(128) char smem[];
    const uint32_t sb = smem_u32(smem);
    const int tid = threadIdx.x, lane = tid & 31, wid = tid >> 5;
    const int wm = wid >> 2, wn = wid & 3;
    const int rowBase = blockIdx.y * 128, colBase = blockIdx.x * 192;

    // stage loader: f32A 1024 granules (4/thread) + B 768 granules (3/thread)
    auto load_stage = [&](int buf, int k0) {
        uint32_t base = sb + G1_SOFF + buf * G1_STAGE;
#pragma unroll
        for (int i = 0; i < 4; i++) {             // f32A: row = g>>3, c16 = g&7
            int g = i * 256 + tid;
            int row = g >> 3, c16 = g & 7;
            CP_ASYNC16(base + row * 144 + c16 * 16,
                       x + (size_t)(rowBase + row) * F_DIM + k0 + c16 * 4);
        }
#pragma unroll
        for (int i = 0; i < 3; i++) {             // B: [32 rows][24 x 16B]
            int gb = i * 256 + tid;
            int row = gb / 24, c16 = gb - row * 24;
            CP_ASYNC16(base + F32A_SZ + row * 400 + c16 * 16,
                       g_w1 + (size_t)(k0 + row) * N1G + colBase + c16 * 8);
        }
        CP_COMMIT();
    };

    // conversion: thread -> row = tid>>1, half-row (16 floats) = tid&1
    const uint32_t cvtSrcOff = G1_SOFF + (tid >> 1) * 144 + (tid & 1) * 64;
    const uint32_t cvtDstOff = (tid >> 1) * 80 + (tid & 1) * 32;
    auto convert = [&](int f32buf, int f16buf) {
        const float4* sp = (const float4*)(smem + cvtSrcOff + f32buf * G1_STAGE);
        float4 v0 = sp[0], v1 = sp[1], v2 = sp[2], v3 = sp[3];
        __half2 h[8];
        h[0] = __floats2half2_rn(v0.x, v0.y);
        h[1] = __floats2half2_rn(v0.z, v0.w);
        h[2] = __floats2half2_rn(v1.x, v1.y);
        h[3] = __floats2half2_rn(v1.z, v1.w);
        h[4] = __floats2half2_rn(v2.x, v2.y);
        h[5] = __floats2half2_rn(v2.z, v2.w);
        h[6] = __floats2half2_rn(v3.x, v3.y);
        h[7] = __floats2half2_rn(v3.z, v3.w);
        uint4* dp = (uint4*)(smem + f16buf * F16A_SZ + cvtDstOff);
        dp[0] = ((uint4*)h)[0];
        dp[1] = ((uint4*)h)[1];
    };

    float acc[4][6][4];
#pragma unroll
    for (int a = 0; a < 4; a++)
#pragma unroll
        for (int b = 0; b < 6; b++)
#pragma unroll
            for (int c = 0; c < 4; c++) acc[a][b][c] = 0.f;

    load_stage(0, 0);
    load_stage(1, 32);
    CP_WAIT(1);                     // stage 0 landed (stage 1 in flight)
    __syncthreads();
    convert(0, 0);                  // f16A[0] <- chunk 0

#pragma unroll 1
    for (int s = 0; s < NSTEPS; s++) {
        __syncthreads();            // all reads of f16A[(s+1)&1] & stage (s-1)%3 done
        if (s + 2 < NSTEPS) {
            load_stage((s + 2) % 3, (s + 2) * 32);
            CP_WAIT(1);             // outstanding {s+1, s+2} -> s+1 landed
        } else if (s + 1 < NSTEPS) {
            CP_WAIT(0);             // last convert needs final stage landed
        }
        if (s + 1 < NSTEPS) convert((s + 1) % 3, (s + 1) & 1);

        uint32_t f16b = sb + (s & 1) * F16A_SZ;
        uint32_t bstage = sb + G1_SOFF + (s % 3) * G1_STAGE + F32A_SZ;
#pragma unroll
        for (int kk = 0; kk < 2; kk++) {
            uint32_t bf[3][4];
            uint32_t brow = bstage + (kk * 16 + (lane & 15)) * 400;
#pragma unroll
            for (int p = 0; p < 3; p++)
                LDSM_X4T(bf[p], brow + (wn * 48 + p * 16 + (lane >> 4) * 8) * 2);
#pragma unroll
            for (int mi = 0; mi < 4; mi++) {
                uint32_t af[4];
                LDSM_X4(af, f16b + (wm * 64 + mi * 16 + (lane & 15)) * 80
                            + (kk * 16 + (lane >> 4) * 8) * 2);
#pragma unroll
                for (int ni = 0; ni < 6; ni++)
                    MMA_F16(acc[mi][ni], af, &bf[ni >> 1][(ni & 1) * 2]);
            }
        }
    }

    // --------------------- LSTM epilogue (register-local) -------------------
    const int c0 = 2 * (lane & 3);
    const int blk0 = (colBase / 24) + wn * 2;
#pragma unroll
    for (int b = 0; b < 2; b++) {
        const int cb = colBase + wn * 48 + b * 24;
        const int h0 = (blk0 + b) * 8 + c0;
        float bi0 = g_b1[cb + c0],      bi1 = g_b1[cb + c0 + 1];
        float bo0 = g_b1[cb + 8 + c0],  bo1 = g_b1[cb + 8 + c0 + 1];
        float ba0 = g_b1[cb + 16 + c0], ba1 = g_b1[cb + 16 + c0 + 1];
#pragma unroll
        for (int mi = 0; mi < 4; mi++) {
            int r0 = rowBase + wm * 64 + mi * 16 + (lane >> 2);
#pragma unroll
            for (int rr = 0; rr < 2; rr++) {
                float zi0 = acc[mi][3 * b + 0][rr * 2 + 0] + bi0;
                float zi1 = acc[mi][3 * b + 0][rr * 2 + 1] + bi1;
                float zo0 = acc[mi][3 * b + 1][rr * 2 + 0] + bo0;
                float zo1 = acc[mi][3 * b + 1][rr * 2 + 1] + bo1;
                float za0 = acc[mi][3 * b + 2][rr * 2 + 0] + ba0;
                float za1 = acc[mi][3 * b + 2][rr * 2 + 1] + ba1;
                float hv0 = fsigm(zo0) * ftanh(fsigm(zi0) * ftanh(za0));
                float hv1 = fsigm(zo1) * ftanh(fsigm(zi1) * ftanh(za1));
                size_t m = (size_t)(r0 + rr * 8);
                *(__half2*)&g_h[m * H_DIM + h0] =
                    __halves2half2(__float2half(hv0), __float2half(hv1));
            }
        }
    }
}

// ---------------------------------------------------------------------------
// GEMM2 (R11 verbatim): out = H @ fco_w + fco_b. CTA 128x128, K=256,
// warp tile 64x32, 4 stages / prefetch-3.
// ---------------------------------------------------------------------------
#define G2_BOFF   10240
#define G2_STAGE  18944
#define G2_SMEM   (4 * G2_STAGE)

__global__ __launch_bounds__(256, 2)
void gemm2(const float* __restrict__ biasg, float* __restrict__ outp) {
    constexpr int NB = H_DIM, NSTEPS = H_DIM / 32;
    extern __shared__ __align__(128) char smem[];
    const uint32_t sb = smem_u32(smem);
    const int tid = threadIdx.x, lane = tid & 31, wid = tid >> 5;
    const int wm = wid >> 2, wn = wid & 3;
    const int rowBase = blockIdx.y * 128, colBase = blockIdx.x * 128;

    auto load_stage = [&](int buf, int k0) {
        uint32_t base = sb + buf * G2_STAGE;
#pragma unroll
        for (int i = 0; i < 4; i++) {
            int g = i * 256 + tid;
            const __half* src;
            uint32_t dst;
            if (g < 512) {
                int row = g >> 2, c16 = g & 3;
                src = g_h + (size_t)(rowBase + row) * H_DIM + k0 + c16 * 8;
                dst = base + row * 80 + c16 * 16;
            } else {
                int gb = g - 512;
                int row = gb >> 4, c16 = gb & 15;
                src = g_f2 + (size_t)(k0 + row) * NB + colBase + c16 * 8;
                dst = base + G2_BOFF + row * 272 + c16 * 16;
            }
            CP_ASYNC16(dst, src);
        }
        CP_COMMIT();
    };

    float acc[4][4][4];
#pragma unroll
    for (int a = 0; a < 4; a++)
#pragma unroll
        for (int b = 0; b < 4; b++)
#pragma unroll
            for (int c = 0; c < 4; c++) acc[a][b][c] = 0.f;

    load_stage(0, 0);
    load_stage(1, 32);
    load_stage(2, 64);

#pragma unroll 1
    for (int s = 0; s < NSTEPS; s++) {
        if (s + 2 < NSTEPS)      CP_WAIT(2);
        else if (s + 1 < NSTEPS) CP_WAIT(1);
        else                     CP_WAIT(0);
        __syncthreads();
        if (s + 3 < NSTEPS) load_stage((s + 3) & 3, (s + 3) * 32);

        uint32_t base = sb + (s & 3) * G2_STAGE;
#pragma unroll
        for (int kk = 0; kk < 2; kk++) {
            uint32_t bf[2][4];
#pragma unroll
            for (int p = 0; p < 2; p++)
                LDSM_X4T(bf[p], base + G2_BOFF + (kk * 16 + (lane & 15)) * 272
                               + (wn * 32 + p * 16 + (lane >> 4) * 8) * 2);
#pragma unroll
            for (int mi = 0; mi < 4; mi++) {
                uint32_t af[4];
                LDSM_X4(af, base + (wm * 64 + mi * 16 + (lane & 15)) * 80
                            + (kk * 16 + (lane >> 4) * 8) * 2);
#pragma unroll
                for (int ni = 0; ni < 4; ni++)
                    MMA_F16(acc[mi][ni], af, &bf[ni >> 1][(ni & 1) * 2]);
            }
        }
    }

#pragma unroll
    for (int mi = 0; mi < 4; mi++) {
        int r0 = rowBase + wm * 64 + mi * 16 + (lane >> 2);
#pragma unroll
        for (int ni = 0; ni < 4; ni++) {
            int col = colBase + wn * 32 + ni * 8 + (lane & 3) * 2;
            float b0 = biasg[col], b1 = biasg[col + 1];
            float2 o0 = {acc[mi][ni][0] + b0, acc[mi][ni][1] + b1};
            float2 o1 = {acc[mi][ni][2] + b0, acc[mi][ni][3] + b1};
            *(float2*)&outp[(size_t)r0 * NB + col] = o0;
            *(float2*)&outp[(size_t)(r0 + 8) * NB + col] = o1;
        }
    }
}

// ---------------------------------------------------------------------------
extern "C" void kernel_launch(void* const* d_in, const int* in_sizes, int n_in,
                              void* d_out, int out_size) {
    const float* x     = (const float*)d_in[0];
    const float* wx_r  = (const float*)d_in[1];
    const float* wx_i  = (const float*)d_in[2];
    const float* wx_j  = (const float*)d_in[3];
    const float* wx_k  = (const float*)d_in[4];
    const float* bx    = (const float*)d_in[5];
    const float* fco_w = (const float*)d_in[10];
    const float* fco_b = (const float*)d_in[11];
    float* out = (float*)d_out;

    build_w1<<<dim3(3, F_DIM), 256>>>(wx_r, wx_i, wx_j, wx_k, bx);
    split_fco<<<(H_DIM * H_DIM) / 256, 256>>>(fco_w);

    cudaFuncSetAttribute(gemm1_lstm,
                         cudaFuncAttributeMaxDynamicSharedMemorySize, G1_SMEM);
    cudaFuncSetAttribute(gemm2,
                         cudaFuncAttributeMaxDynamicSharedMemorySize, G2_SMEM);

    gemm1_lstm<<<dim3(N1G / 192, B_DIM / 128), 256, G1_SMEM>>>(x);
    gemm2<<<dim3(H_DIM / 128, B_DIM / 128), 256, G2_SMEM>>>(fco_b, out);
}

// round 15
// speedup vs baseline: 5.6696x; 1.1714x over previous
#include <cuda_runtime.h>
#include <cuda_fp16.h>
#include <stdint.h>

// ============================================================================
// QuaternionLSTM single step, h0=c0=0 (uh_* dead; forget-gate columns dropped):
//   Z = x @ W1 + b1  (W1 = quaternion-expanded wx, gates {i,o,a}, N=768)
//   H = sigmoid(z_o) * tanh( sigmoid(z_i) * tanh(z_a) )
//   out = H @ fco_w + fco_b
// fp16 mma.sync, f32 accum (rel_err ~4.6e-4).
// R15: restore the measured-best R11 configuration (207.1us) verbatim —
// gemm1: fused fp32->fp16 A conversion, single f16A buffer, TWO barriers per
// chunk, 3-stage cp.async (wait(1) targets a stage issued 2 iters back);
// gemm2: 4-stage. Single micro-reorder: load_stage(s+2) issued BEFORE the
// convert block so cp.asyncs fly during the convert LDS/CVT/STS chain.
// ============================================================================

#define B_DIM 32768
#define F_DIM 1024
#define H_DIM 256
#define N1G   768            // 3 gates x 256

__device__ __align__(16) __half g_w1[F_DIM * N1G];           // [k][n_perm]
__device__ float g_b1[N1G];
__device__ __align__(16) __half g_h[(size_t)B_DIM * H_DIM];
__device__ __align__(16) __half g_f2[H_DIM * H_DIM];          // [k][n]

// ---------------------------------------------------------------------------
__device__ __forceinline__ uint32_t smem_u32(const void* p) {
    uint32_t a;
    asm("{ .reg .u64 t; cvta.to.shared.u64 t, %1; cvt.u32.u64 %0, t; }" : "=r"(a) : "l"(p));
    return a;
}

#define LDSM_X4(r, a) \
    asm volatile("ldmatrix.sync.aligned.m8n8.x4.shared.b16 {%0,%1,%2,%3}, [%4];" \
        : "=r"((r)[0]), "=r"((r)[1]), "=r"((r)[2]), "=r"((r)[3]) : "r"(a))
#define LDSM_X4T(r, a) \
    asm volatile("ldmatrix.sync.aligned.m8n8.x4.trans.shared.b16 {%0,%1,%2,%3}, [%4];" \
        : "=r"((r)[0]), "=r"((r)[1]), "=r"((r)[2]), "=r"((r)[3]) : "r"(a))
#define MMA_F16(d, a, b) \
    asm volatile("mma.sync.aligned.m16n8k16.row.col.f32.f16.f16.f32 " \
        "{%0,%1,%2,%3}, {%4,%5,%6,%7}, {%8,%9}, {%0,%1,%2,%3};" \
        : "+f"((d)[0]), "+f"((d)[1]), "+f"((d)[2]), "+f"((d)[3]) \
        : "r"((a)[0]), "r"((a)[1]), "r"((a)[2]), "r"((a)[3]), "r"((b)[0]), "r"((b)[1]))
#define CP_ASYNC16(dst, src) \
    asm volatile("cp.async.cg.shared.global [%0], [%1], 16;" :: "r"(dst), "l"(src) : "memory")
#define CP_COMMIT() asm volatile("cp.async.commit_group;" ::: "memory")
#define CP_WAIT(n)  asm volatile("cp.async.wait_group %0;" :: "n"(n) : "memory")

__device__ __forceinline__ float fsigm(float z) {
    return __fdividef(1.f, 1.f + __expf(-z));
}
__device__ __forceinline__ float ftanh(float x) {
    float xc = fminf(fmaxf(x, -15.f), 15.f);
    float e = __expf(2.f * xc);
    return __fdividef(e - 1.f, e + 1.f);
}

// ---------------------------------------------------------------------------
// Prep kernels
// ---------------------------------------------------------------------------
__global__ void build_w1(const float* __restrict__ wr, const float* __restrict__ wi,
                         const float* __restrict__ wj, const float* __restrict__ wk,
                         const float* __restrict__ bx) {
    int rem = blockIdx.x * blockDim.x + threadIdx.x;   // 0..767
    int f = blockIdx.y;
    int blk = rem / 24;
    int r24 = rem - blk * 24;
    int g1 = r24 >> 3, hh = r24 & 7;
    int h = blk * 8 + hh;
    int gate = g1 + 1;                      // skip forget gate (index 0)
    int qout = h >> 6, h4 = h & 63;
    int qin = f >> 8, f4 = f & 255;
    int comp = qin ^ qout;
    const float* a = (comp & 2) ? ((comp & 1) ? wk : wj)
                                : ((comp & 1) ? wi : wr);
    float w = a[gate * (256 * 64) + f4 * 64 + h4];
    float v = ((0x5390u >> ((qin << 2) + qout)) & 1u) ? -w : w;
    g_w1[f * N1G + rem] = __float2half(v);
    if (f == 0) g_b1[rem] = bx[gate * H_DIM + h];
}

__global__ void split_fco(const float* __restrict__ w) {
    int idx = blockIdx.x * blockDim.x + threadIdx.x;  // over 65536, [k][n]
    g_f2[idx] = __float2half(w[idx]);
}

// ---------------------------------------------------------------------------
// GEMM1 + fused fp32->fp16 A conversion + LSTM epilogue (R11 structure).
// CTA 128x192, K-chunk 32, 8 warps 2x4 (warp tile 64x48), 2 CTAs/SM.
// SMEM: f16A[10240] single buffer, 3 stages x { f32A 18432, B 12800 }.
// Per chunk: wait(1) -> sync -> load(s+2) -> convert(s) -> sync -> MMA(s).
// ---------------------------------------------------------------------------
#define F16A_SZ   10240
#define F32A_SZ   18432
#define G1_BSZ    12800
#define G1_STAGE  (F32A_SZ + G1_BSZ)              // 31232
#define G1_SMEM   (F16A_SZ + 3 * G1_STAGE)        // 103936

__global__ __launch_bounds__(256, 2)
void gemm1_lstm(const float* __restrict__ x) {
    constexpr int NSTEPS = F_DIM / 32;            // 32
    extern __shared__ __align__(128) char smem[];
    const uint32_t sb = smem_u32(smem);
    const int tid = threadIdx.x, lane = tid & 31, wid = tid >> 5;
    const int wm = wid >> 2, wn = wid & 3;
    const int rowBase = blockIdx.y * 128, colBase = blockIdx.x * 192;

    // stage loader: f32A 1024 granules (4/thread) + B 768 granules (3/thread)
    auto load_stage = [&](int buf, int k0) {
        uint32_t base = sb + F16A_SZ + buf * G1_STAGE;
#pragma unroll
        for (int i = 0; i < 4; i++) {             // f32A: row = g>>3, c16 = g&7
            int g = i * 256 + tid;
            int row = g >> 3, c16 = g & 7;
            CP_ASYNC16(base + row * 144 + c16 * 16,
                       x + (size_t)(rowBase + row) * F_DIM + k0 + c16 * 4);
        }
#pragma unroll
        for (int i = 0; i < 3; i++) {             // B: [32 rows][24 x 16B]
            int gb = i * 256 + tid;
            int row = gb / 24, c16 = gb - row * 24;
            CP_ASYNC16(base + F32A_SZ + row * 400 + c16 * 16,
                       g_w1 + (size_t)(k0 + row) * N1G + colBase + c16 * 8);
        }
        CP_COMMIT();
    };

    // conversion: thread -> row = tid>>1, half-row (16 floats) = tid&1
    const uint32_t cvtSrcOff = F16A_SZ + (tid >> 1) * 144 + (tid & 1) * 64;
    const uint32_t cvtDstOff = (tid >> 1) * 80 + (tid & 1) * 32;

    float acc[4][6][4];
#pragma unroll
    for (int a = 0; a < 4; a++)
#pragma unroll
        for (int b = 0; b < 6; b++)
#pragma unroll
            for (int c = 0; c < 4; c++) acc[a][b][c] = 0.f;

    load_stage(0, 0);
    load_stage(1, 32);

#pragma unroll 1
    for (int s = 0; s < NSTEPS; s++) {
        if (s + 1 < NSTEPS) CP_WAIT(1); else CP_WAIT(0);
        __syncthreads();                 // stage s landed; f16A reads of s-1 done
        if (s + 2 < NSTEPS) load_stage((s + 2) % 3, (s + 2) * 32);

        // ---- convert fp32 A chunk s -> fp16 A buffer (cp.asyncs in flight) ----
        {
            const float4* sp = (const float4*)(smem + cvtSrcOff + (s % 3) * G1_STAGE);
            float4 v0 = sp[0], v1 = sp[1], v2 = sp[2], v3 = sp[3];
            __half h[16] = {
                __float2half(v0.x), __float2half(v0.y), __float2half(v0.z), __float2half(v0.w),
                __float2half(v1.x), __float2half(v1.y), __float2half(v1.z), __float2half(v1.w),
                __float2half(v2.x), __float2half(v2.y), __float2half(v2.z), __float2half(v2.w),
                __float2half(v3.x), __float2half(v3.y), __float2half(v3.z), __float2half(v3.w)};
            ((uint4*)(smem + cvtDstOff))[0] = ((uint4*)h)[0];
            ((uint4*)(smem + cvtDstOff))[1] = ((uint4*)h)[1];
        }
        __syncthreads();                 // f16A visible to all warps

        uint32_t bstage = sb + F16A_SZ + (s % 3) * G1_STAGE + F32A_SZ;
#pragma unroll
        for (int kk = 0; kk < 2; kk++) {
            uint32_t bf[3][4];
            uint32_t brow = bstage + (kk * 16 + (lane & 15)) * 400;
#pragma unroll
            for (int p = 0; p < 3; p++)
                LDSM_X4T(bf[p], brow + (wn * 48 + p * 16 + (lane >> 4) * 8) * 2);
#pragma unroll
            for (int mi = 0; mi < 4; mi++) {
                uint32_t af[4];
                LDSM_X4(af, sb + (wm * 64 + mi * 16 + (lane & 15)) * 80
                            + (kk * 16 + (lane >> 4) * 8) * 2);
#pragma unroll
                for (int ni = 0; ni < 6; ni++)
                    MMA_F16(acc[mi][ni], af, &bf[ni >> 1][(ni & 1) * 2]);
            }
        }
    }

    // --------------------- LSTM epilogue (register-local) -------------------
    const int c0 = 2 * (lane & 3);
    const int blk0 = (colBase / 24) + wn * 2;
#pragma unroll
    for (int b = 0; b < 2; b++) {
        const int cb = colBase + wn * 48 + b * 24;
        const int h0 = (blk0 + b) * 8 + c0;
        float bi0 = g_b1[cb + c0],      bi1 = g_b1[cb + c0 + 1];
        float bo0 = g_b1[cb + 8 + c0],  bo1 = g_b1[cb + 8 + c0 + 1];
        float ba0 = g_b1[cb + 16 + c0], ba1 = g_b1[cb + 16 + c0 + 1];
#pragma unroll
        for (int mi = 0; mi < 4; mi++) {
            int r0 = rowBase + wm * 64 + mi * 16 + (lane >> 2);
#pragma unroll
            for (int rr = 0; rr < 2; rr++) {
                float zi0 = acc[mi][3 * b + 0][rr * 2 + 0] + bi0;
                float zi1 = acc[mi][3 * b + 0][rr * 2 + 1] + bi1;
                float zo0 = acc[mi][3 * b + 1][rr * 2 + 0] + bo0;
                float zo1 = acc[mi][3 * b + 1][rr * 2 + 1] + bo1;
                float za0 = acc[mi][3 * b + 2][rr * 2 + 0] + ba0;
                float za1 = acc[mi][3 * b + 2][rr * 2 + 1] + ba1;
                float hv0 = fsigm(zo0) * ftanh(fsigm(zi0) * ftanh(za0));
                float hv1 = fsigm(zo1) * ftanh(fsigm(zi1) * ftanh(za1));
                size_t m = (size_t)(r0 + rr * 8);
                *(__half2*)&g_h[m * H_DIM + h0] =
                    __halves2half2(__float2half(hv0), __float2half(hv1));
            }
        }
    }
}

// ---------------------------------------------------------------------------
// GEMM2 (R11 verbatim): out = H @ fco_w + fco_b. CTA 128x128, K=256,
// warp tile 64x32, 4 stages / prefetch-3.
// ---------------------------------------------------------------------------
#define G2_BOFF   10240
#define G2_STAGE  18944
#define G2_SMEM   (4 * G2_STAGE)

__global__ __launch_bounds__(256, 2)
void gemm2(const float* __restrict__ biasg, float* __restrict__ outp) {
    constexpr int NB = H_DIM, NSTEPS = H_DIM / 32;
    extern __shared__ __align__(128) char smem[];
    const uint32_t sb = smem_u32(smem);
    const int tid = threadIdx.x, lane = tid & 31, wid = tid >> 5;
    const int wm = wid >> 2, wn = wid & 3;
    const int rowBase = blockIdx.y * 128, colBase = blockIdx.x * 128;

    auto load_stage = [&](int buf, int k0) {
        uint32_t base = sb + buf * G2_STAGE;
#pragma unroll
        for (int i = 0; i < 4; i++) {
            int g = i * 256 + tid;
            const __half* src;
            uint32_t dst;
            if (g < 512) {
                int row = g >> 2, c16 = g & 3;
                src = g_h + (size_t)(rowBase + row) * H_DIM + k0 + c16 * 8;
                dst = base + row * 80 + c16 * 16;
            } else {
                int gb = g - 512;
                int row = gb >> 4, c16 = gb & 15;
                src = g_f2 + (size_t)(k0 + row) * NB + colBase + c16 * 8;
                dst = base + G2_BOFF + row * 272 + c16 * 16;
            }
            CP_ASYNC16(dst, src);
        }
        CP_COMMIT();
    };

    float acc[4][4][4];
#pragma unroll
    for (int a = 0; a < 4; a++)
#pragma unroll
        for (int b = 0; b < 4; b++)
#pragma unroll
            for (int c = 0; c < 4; c++) acc[a][b][c] = 0.f;

    load_stage(0, 0);
    load_stage(1, 32);
    load_stage(2, 64);

#pragma unroll 1
    for (int s = 0; s < NSTEPS; s++) {
        if (s + 2 < NSTEPS)      CP_WAIT(2);
        else if (s + 1 < NSTEPS) CP_WAIT(1);
        else                     CP_WAIT(0);
        __syncthreads();
        if (s + 3 < NSTEPS) load_stage((s + 3) & 3, (s + 3) * 32);

        uint32_t base = sb + (s & 3) * G2_STAGE;
#pragma unroll
        for (int kk = 0; kk < 2; kk++) {
            uint32_t bf[2][4];
#pragma unroll
            for (int p = 0; p < 2; p++)
                LDSM_X4T(bf[p], base + G2_BOFF + (kk * 16 + (lane & 15)) * 272
                               + (wn * 32 + p * 16 + (lane >> 4) * 8) * 2);
#pragma unroll
            for (int mi = 0; mi < 4; mi++) {
                uint32_t af[4];
                LDSM_X4(af, base + (wm * 64 + mi * 16 + (lane & 15)) * 80
                            + (kk * 16 + (lane >> 4) * 8) * 2);
#pragma unroll
                for (int ni = 0; ni < 4; ni++)
                    MMA_F16(acc[mi][ni], af, &bf[ni >> 1][(ni & 1) * 2]);
            }
        }
    }

#pragma unroll
    for (int mi = 0; mi < 4; mi++) {
        int r0 = rowBase + wm * 64 + mi * 16 + (lane >> 2);
#pragma unroll
        for (int ni = 0; ni < 4; ni++) {
            int col = colBase + wn * 32 + ni * 8 + (lane & 3) * 2;
            float b0 = biasg[col], b1 = biasg[col + 1];
            float2 o0 = {acc[mi][ni][0] + b0, acc[mi][ni][1] + b1};
            float2 o1 = {acc[mi][ni][2] + b0, acc[mi][ni][3] + b1};
            *(float2*)&outp[(size_t)r0 * NB + col] = o0;
            *(float2*)&outp[(size_t)(r0 + 8) * NB + col] = o1;
        }
    }
}

// ---------------------------------------------------------------------------
extern "C" void kernel_launch(void* const* d_in, const int* in_sizes, int n_in,
                              void* d_out, int out_size) {
    const float* x     = (const float*)d_in[0];
    const float* wx_r  = (const float*)d_in[1];
    const float* wx_i  = (const float*)d_in[2];
    const float* wx_j  = (const float*)d_in[3];
    const float* wx_k  = (const float*)d_in[4];
    const float* bx    = (const float*)d_in[5];
    const float* fco_w = (const float*)d_in[10];
    const float* fco_b = (const float*)d_in[11];
    float* out = (float*)d_out;

    build_w1<<<dim3(3, F_DIM), 256>>>(wx_r, wx_i, wx_j, wx_k, bx);
    split_fco<<<(H_DIM * H_DIM) / 256, 256>>>(fco_w);

    cudaFuncSetAttribute(gemm1_lstm,
                         cudaFuncAttributeMaxDynamicSharedMemorySize, G1_SMEM);
    cudaFuncSetAttribute(gemm2,
                         cudaFuncAttributeMaxDynamicSharedMemorySize, G2_SMEM);

    gemm1_lstm<<<dim3(N1G / 192, B_DIM / 128), 256, G1_SMEM>>>(x);
    gemm2<<<dim3(H_DIM / 128, B_DIM / 128), 256, G2_SMEM>>>(fco_b, out);
}

// round 16
// speedup vs baseline: 5.6740x; 1.0008x over previous
#include <cuda_runtime.h>
#include <cuda_fp16.h>
#include <stdint.h>

// ============================================================================
// QuaternionLSTM single step, h0=c0=0 (uh_* dead; forget-gate columns dropped):
//   Z = x @ W1 + b1  (W1 = quaternion-expanded wx, gates {i,o,a}, N=768)
//   H = sigmoid(z_o) * tanh( sigmoid(z_i) * tanh(z_a) )
//   out = H @ fco_w + fco_b
// fp16 mma.sync, f32 accum (rel_err ~4.6e-4).
// R16: gemm1 = R15 verbatim (measured best ~173us, frozen). gemm2 rebuilt for
// latency-hiding: 512 threads, 16 warps 4x4 (warp tile 32x32), acc 32 regs,
// 2 CTAs/SM -> 32 warps/SM (occ 21.7%->~44%). gemm2 was latency-bound
// (tensor 29%, L1 39%, nothing saturated) with L1 headroom for the 2x LDS.
// ============================================================================

#define B_DIM 32768
#define F_DIM 1024
#define H_DIM 256
#define N1G   768            // 3 gates x 256

__device__ __align__(16) __half g_w1[F_DIM * N1G];           // [k][n_perm]
__device__ float g_b1[N1G];
__device__ __align__(16) __half g_h[(size_t)B_DIM * H_DIM];
__device__ __align__(16) __half g_f2[H_DIM * H_DIM];          // [k][n]

// ---------------------------------------------------------------------------
__device__ __forceinline__ uint32_t smem_u32(const void* p) {
    uint32_t a;
    asm("{ .reg .u64 t; cvta.to.shared.u64 t, %1; cvt.u32.u64 %0, t; }" : "=r"(a) : "l"(p));
    return a;
}

#define LDSM_X4(r, a) \
    asm volatile("ldmatrix.sync.aligned.m8n8.x4.shared.b16 {%0,%1,%2,%3}, [%4];" \
        : "=r"((r)[0]), "=r"((r)[1]), "=r"((r)[2]), "=r"((r)[3]) : "r"(a))
#define LDSM_X4T(r, a) \
    asm volatile("ldmatrix.sync.aligned.m8n8.x4.trans.shared.b16 {%0,%1,%2,%3}, [%4];" \
        : "=r"((r)[0]), "=r"((r)[1]), "=r"((r)[2]), "=r"((r)[3]) : "r"(a))
#define MMA_F16(d, a, b) \
    asm volatile("mma.sync.aligned.m16n8k16.row.col.f32.f16.f16.f32 " \
        "{%0,%1,%2,%3}, {%4,%5,%6,%7}, {%8,%9}, {%0,%1,%2,%3};" \
        : "+f"((d)[0]), "+f"((d)[1]), "+f"((d)[2]), "+f"((d)[3]) \
        : "r"((a)[0]), "r"((a)[1]), "r"((a)[2]), "r"((a)[3]), "r"((b)[0]), "r"((b)[1]))
#define CP_ASYNC16(dst, src) \
    asm volatile("cp.async.cg.shared.global [%0], [%1], 16;" :: "r"(dst), "l"(src) : "memory")
#define CP_COMMIT() asm volatile("cp.async.commit_group;" ::: "memory")
#define CP_WAIT(n)  asm volatile("cp.async.wait_group %0;" :: "n"(n) : "memory")

__device__ __forceinline__ float fsigm(float z) {
    return __fdividef(1.f, 1.f + __expf(-z));
}
__device__ __forceinline__ float ftanh(float x) {
    float xc = fminf(fmaxf(x, -15.f), 15.f);
    float e = __expf(2.f * xc);
    return __fdividef(e - 1.f, e + 1.f);
}

// ---------------------------------------------------------------------------
// Prep kernels
// ---------------------------------------------------------------------------
__global__ void build_w1(const float* __restrict__ wr, const float* __restrict__ wi,
                         const float* __restrict__ wj, const float* __restrict__ wk,
                         const float* __restrict__ bx) {
    int rem = blockIdx.x * blockDim.x + threadIdx.x;   // 0..767
    int f = blockIdx.y;
    int blk = rem / 24;
    int r24 = rem - blk * 24;
    int g1 = r24 >> 3, hh = r24 & 7;
    int h = blk * 8 + hh;
    int gate = g1 + 1;                      // skip forget gate (index 0)
    int qout = h >> 6, h4 = h & 63;
    int qin = f >> 8, f4 = f & 255;
    int comp = qin ^ qout;
    const float* a = (comp & 2) ? ((comp & 1) ? wk : wj)
                                : ((comp & 1) ? wi : wr);
    float w = a[gate * (256 * 64) + f4 * 64 + h4];
    float v = ((0x5390u >> ((qin << 2) + qout)) & 1u) ? -w : w;
    g_w1[f * N1G + rem] = __float2half(v);
    if (f == 0) g_b1[rem] = bx[gate * H_DIM + h];
}

__global__ void split_fco(const float* __restrict__ w) {
    int idx = blockIdx.x * blockDim.x + threadIdx.x;  // over 65536, [k][n]
    g_f2[idx] = __float2half(w[idx]);
}

// ---------------------------------------------------------------------------
// GEMM1 + fused fp32->fp16 A conversion + LSTM epilogue (R15 verbatim).
// CTA 128x192, K-chunk 32, 8 warps 2x4 (warp tile 64x48), 2 CTAs/SM.
// SMEM: f16A[10240] single buffer, 3 stages x { f32A 18432, B 12800 }.
// Per chunk: wait(1) -> sync -> load(s+2) -> convert(s) -> sync -> MMA(s).
// ---------------------------------------------------------------------------
#define F16A_SZ   10240
#define F32A_SZ   18432
#define G1_BSZ    12800
#define G1_STAGE  (F32A_SZ + G1_BSZ)              // 31232
#define G1_SMEM   (F16A_SZ + 3 * G1_STAGE)        // 103936

__global__ __launch_bounds__(256, 2)
void gemm1_lstm(const float* __restrict__ x) {
    constexpr int NSTEPS = F_DIM / 32;            // 32
    extern __shared__ __align__(128) char smem[];
    const uint32_t sb = smem_u32(smem);
    const int tid = threadIdx.x, lane = tid & 31, wid = tid >> 5;
    const int wm = wid >> 2, wn = wid & 3;
    const int rowBase = blockIdx.y * 128, colBase = blockIdx.x * 192;

    auto load_stage = [&](int buf, int k0) {
        uint32_t base = sb + F16A_SZ + buf * G1_STAGE;
#pragma unroll
        for (int i = 0; i < 4; i++) {             // f32A: row = g>>3, c16 = g&7
            int g = i * 256 + tid;
            int row = g >> 3, c16 = g & 7;
            CP_ASYNC16(base + row * 144 + c16 * 16,
                       x + (size_t)(rowBase + row) * F_DIM + k0 + c16 * 4);
        }
#pragma unroll
        for (int i = 0; i < 3; i++) {             // B: [32 rows][24 x 16B]
            int gb = i * 256 + tid;
            int row = gb / 24, c16 = gb - row * 24;
            CP_ASYNC16(base + F32A_SZ + row * 400 + c16 * 16,
                       g_w1 + (size_t)(k0 + row) * N1G + colBase + c16 * 8);
        }
        CP_COMMIT();
    };

    const uint32_t cvtSrcOff = F16A_SZ + (tid >> 1) * 144 + (tid & 1) * 64;
    const uint32_t cvtDstOff = (tid >> 1) * 80 + (tid & 1) * 32;

    float acc[4][6][4];
#pragma unroll
    for (int a = 0; a < 4; a++)
#pragma unroll
        for (int b = 0; b < 6; b++)
#pragma unroll
            for (int c = 0; c < 4; c++) acc[a][b][c] = 0.f;

    load_stage(0, 0);
    load_stage(1, 32);

#pragma unroll 1
    for (int s = 0; s < NSTEPS; s++) {
        if (s + 1 < NSTEPS) CP_WAIT(1); else CP_WAIT(0);
        __syncthreads();                 // stage s landed; f16A reads of s-1 done
        if (s + 2 < NSTEPS) load_stage((s + 2) % 3, (s + 2) * 32);

        {   // convert fp32 A chunk s -> fp16 A buffer (cp.asyncs in flight)
            const float4* sp = (const float4*)(smem + cvtSrcOff + (s % 3) * G1_STAGE);
            float4 v0 = sp[0], v1 = sp[1], v2 = sp[2], v3 = sp[3];
            __half h[16] = {
                __float2half(v0.x), __float2half(v0.y), __float2half(v0.z), __float2half(v0.w),
                __float2half(v1.x), __float2half(v1.y), __float2half(v1.z), __float2half(v1.w),
                __float2half(v2.x), __float2half(v2.y), __float2half(v2.z), __float2half(v2.w),
                __float2half(v3.x), __float2half(v3.y), __float2half(v3.z), __float2half(v3.w)};
            ((uint4*)(smem + cvtDstOff))[0] = ((uint4*)h)[0];
            ((uint4*)(smem + cvtDstOff))[1] = ((uint4*)h)[1];
        }
        __syncthreads();                 // f16A visible to all warps

        uint32_t bstage = sb + F16A_SZ + (s % 3) * G1_STAGE + F32A_SZ;
#pragma unroll
        for (int kk = 0; kk < 2; kk++) {
            uint32_t bf[3][4];
            uint32_t brow = bstage + (kk * 16 + (lane & 15)) * 400;
#pragma unroll
            for (int p = 0; p < 3; p++)
                LDSM_X4T(bf[p], brow + (wn * 48 + p * 16 + (lane >> 4) * 8) * 2);
#pragma unroll
            for (int mi = 0; mi < 4; mi++) {
                uint32_t af[4];
                LDSM_X4(af, sb + (wm * 64 + mi * 16 + (lane & 15)) * 80
                            + (kk * 16 + (lane >> 4) * 8) * 2);
#pragma unroll
                for (int ni = 0; ni < 6; ni++)
                    MMA_F16(acc[mi][ni], af, &bf[ni >> 1][(ni & 1) * 2]);
            }
        }
    }

    // --------------------- LSTM epilogue (register-local) -------------------
    const int c0 = 2 * (lane & 3);
    const int blk0 = (colBase / 24) + wn * 2;
#pragma unroll
    for (int b = 0; b < 2; b++) {
        const int cb = colBase + wn * 48 + b * 24;
        const int h0 = (blk0 + b) * 8 + c0;
        float bi0 = g_b1[cb + c0],      bi1 = g_b1[cb + c0 + 1];
        float bo0 = g_b1[cb + 8 + c0],  bo1 = g_b1[cb + 8 + c0 + 1];
        float ba0 = g_b1[cb + 16 + c0], ba1 = g_b1[cb + 16 + c0 + 1];
#pragma unroll
        for (int mi = 0; mi < 4; mi++) {
            int r0 = rowBase + wm * 64 + mi * 16 + (lane >> 2);
#pragma unroll
            for (int rr = 0; rr < 2; rr++) {
                float zi0 = acc[mi][3 * b + 0][rr * 2 + 0] + bi0;
                float zi1 = acc[mi][3 * b + 0][rr * 2 + 1] + bi1;
                float zo0 = acc[mi][3 * b + 1][rr * 2 + 0] + bo0;
                float zo1 = acc[mi][3 * b + 1][rr * 2 + 1] + bo1;
                float za0 = acc[mi][3 * b + 2][rr * 2 + 0] + ba0;
                float za1 = acc[mi][3 * b + 2][rr * 2 + 1] + ba1;
                float hv0 = fsigm(zo0) * ftanh(fsigm(zi0) * ftanh(za0));
                float hv1 = fsigm(zo1) * ftanh(fsigm(zi1) * ftanh(za1));
                size_t m = (size_t)(r0 + rr * 8);
                *(__half2*)&g_h[m * H_DIM + h0] =
                    __halves2half2(__float2half(hv0), __float2half(hv1));
            }
        }
    }
}

// ---------------------------------------------------------------------------
// GEMM2: out = H @ fco_w + fco_b. CTA 128x128, 512 threads, 16 warps 4x4
// (warp tile 32x32, acc 32 regs), K=256, 4 stages / prefetch-3, 2 CTAs/SM.
// ---------------------------------------------------------------------------
#define G2_BOFF   10240
#define G2_STAGE  18944
#define G2_SMEM   (4 * G2_STAGE)

__global__ __launch_bounds__(512, 2)
void gemm2(const float* __restrict__ biasg, float* __restrict__ outp) {
    constexpr int NB = H_DIM, NSTEPS = H_DIM / 32;
    extern __shared__ __align__(128) char smem[];
    const uint32_t sb = smem_u32(smem);
    const int tid = threadIdx.x, lane = tid & 31, wid = tid >> 5;
    const int wm = wid >> 2, wn = wid & 3;      // wm:0-3 (32 rows), wn:0-3 (32 cols)
    const int rowBase = blockIdx.y * 128, colBase = blockIdx.x * 128;

    // loader: A 512 granules (1/thread) + B 512 granules (1/thread)
    auto load_stage = [&](int buf, int k0) {
        uint32_t base = sb + buf * G2_STAGE;
        {   // A: row = tid>>2, c16 = tid&3
            int row = tid >> 2, c16 = tid & 3;
            CP_ASYNC16(base + row * 80 + c16 * 16,
                       g_h + (size_t)(rowBase + row) * H_DIM + k0 + c16 * 8);
        }
        {   // B: row = tid>>4, c16 = tid&15
            int row = tid >> 4, c16 = tid & 15;
            CP_ASYNC16(base + G2_BOFF + row * 272 + c16 * 16,
                       g_f2 + (size_t)(k0 + row) * NB + colBase + c16 * 8);
        }
        CP_COMMIT();
    };

    const uint32_t aBase = (wm * 32 + (lane & 15)) * 80 + (lane >> 4) * 16;
    const uint32_t bBase = G2_BOFF + (lane & 15) * 272
                         + (wn * 32 + (lane >> 4) * 8) * 2;

    float acc[2][4][4];
#pragma unroll
    for (int a = 0; a < 2; a++)
#pragma unroll
        for (int b = 0; b < 4; b++)
#pragma unroll
            for (int c = 0; c < 4; c++) acc[a][b][c] = 0.f;

    load_stage(0, 0);
    load_stage(1, 32);
    load_stage(2, 64);

#pragma unroll 1
    for (int s = 0; s < NSTEPS; s++) {
        if (s + 2 < NSTEPS)      CP_WAIT(2);
        else if (s + 1 < NSTEPS) CP_WAIT(1);
        else                     CP_WAIT(0);
        __syncthreads();
        if (s + 3 < NSTEPS) load_stage((s + 3) & 3, (s + 3) * 32);

        uint32_t base = sb + (s & 3) * G2_STAGE;
#pragma unroll
        for (int kk = 0; kk < 2; kk++) {
            uint32_t bf[2][4];
#pragma unroll
            for (int p = 0; p < 2; p++)
                LDSM_X4T(bf[p], base + bBase + kk * 4352 + p * 32);
#pragma unroll
            for (int mi = 0; mi < 2; mi++) {
                uint32_t af[4];
                LDSM_X4(af, base + aBase + mi * 1280 + kk * 32);
#pragma unroll
                for (int ni = 0; ni < 4; ni++)
                    MMA_F16(acc[mi][ni], af, &bf[ni >> 1][(ni & 1) * 2]);
            }
        }
    }

#pragma unroll
    for (int mi = 0; mi < 2; mi++) {
        int r0 = rowBase + wm * 32 + mi * 16 + (lane >> 2);
#pragma unroll
        for (int ni = 0; ni < 4; ni++) {
            int col = colBase + wn * 32 + ni * 8 + (lane & 3) * 2;
            float b0 = biasg[col], b1 = biasg[col + 1];
            float2 o0 = {acc[mi][ni][0] + b0, acc[mi][ni][1] + b1};
            float2 o1 = {acc[mi][ni][2] + b0, acc[mi][ni][3] + b1};
            *(float2*)&outp[(size_t)r0 * NB + col] = o0;
            *(float2*)&outp[(size_t)(r0 + 8) * NB + col] = o1;
        }
    }
}

// ---------------------------------------------------------------------------
extern "C" void kernel_launch(void* const* d_in, const int* in_sizes, int n_in,
                              void* d_out, int out_size) {
    const float* x     = (const float*)d_in[0];
    const float* wx_r  = (const float*)d_in[1];
    const float* wx_i  = (const float*)d_in[2];
    const float* wx_j  = (const float*)d_in[3];
    const float* wx_k  = (const float*)d_in[4];
    const float* bx    = (const float*)d_in[5];
    const float* fco_w = (const float*)d_in[10];
    const float* fco_b = (const float*)d_in[11];
    float* out = (float*)d_out;

    build_w1<<<dim3(3, F_DIM), 256>>>(wx_r, wx_i, wx_j, wx_k, bx);
    split_fco<<<(H_DIM * H_DIM) / 256, 256>>>(fco_w);

    cudaFuncSetAttribute(gemm1_lstm,
                         cudaFuncAttributeMaxDynamicSharedMemorySize, G1_SMEM);
    cudaFuncSetAttribute(gemm2,
                         cudaFuncAttributeMaxDynamicSharedMemorySize, G2_SMEM);

    gemm1_lstm<<<dim3(N1G / 192, B_DIM / 128), 256, G1_SMEM>>>(x);
    gemm2<<<dim3(H_DIM / 128, B_DIM / 128), 512, G2_SMEM>>>(fco_b, out);
}